// round 14
// baseline (speedup 1.0000x reference)
#include <cuda_runtime.h>
#include <cstdint>
#include <math.h>

#define BB 32
#define DD 1024
#define HH 64
#define OO 1000
#define EE 6
#define NBLK 256
#define NTHR 128
#define CLUSTER 8
// Padded x: 32-float chunks padded by 4 -> chunk dg starts at float dg*36.
#define XSP (DD + DD / 8)

__device__ __forceinline__ void fma4(float4& acc, float v, const float4& w) {
    acc.x += v * w.x; acc.y += v * w.y; acc.z += v * w.z; acc.w += v * w.w;
}

__device__ __forceinline__ unsigned int smem_u32(const void* p) {
    unsigned int a;
    asm("{ .reg .u64 t; cvta.to.shared.u64 t, %1; cvt.u32.u64 %0, t; }"
        : "=r"(a) : "l"(p));
    return a;
}

// Store one float into the same smem offset of cluster CTA `rank`.
__device__ __forceinline__ void dsmem_store(unsigned int local_addr, int rank, float v) {
    unsigned int rem;
    asm volatile("mapa.shared::cluster.u32 %0, %1, %2;"
                 : "=r"(rem) : "r"(local_addr), "r"(rank));
    asm volatile("st.shared::cluster.f32 [%0], %1;"
                 :: "r"(rem), "f"(v) : "memory");
}

__global__ void __launch_bounds__(NTHR) __cluster_dims__(CLUSTER, 1, 1)
moe_fused(const float* __restrict__ x,
          const float* __restrict__ gw,
          const float* __restrict__ gb,
          const float* __restrict__ w1,
          const float* __restrict__ b1,
          const float* __restrict__ w2,
          const float* __restrict__ b2,
          float* __restrict__ out) {
    const int bid = blockIdx.x;
    const int tid = threadIdx.x;
    const int warp = tid >> 5, lane = tid & 31;

    __shared__ __align__(16) float xs[XSP];         // padded x row
    __shared__ __align__(16) float part[4][16];     // (warp, col) fc1 partials
    __shared__ __align__(16) float hs[2 * HH];      // row b's full h (both slots)
    __shared__ float logit[EE];

    // Cluster = the 8 blocks of row b.
    // Phase-1 role: k = j>>2 (expert slot), cq = j&3 (16-col quarter).
    // Phase-2 role: oc = j (o-chunk: 7x128 + 104).
    const int b = bid >> 3, j = bid & 7;
    const int k = j >> 2, cq = j & 3;
    const int oc = j;

    // ---- stage x to padded smem (2 passes) + gate logits from GLOBAL x -----
    {
        int i0 = tid, i1 = tid + 128;
        ((float4*)xs)[i0 + (i0 >> 3)] = ((const float4*)(x + b * DD))[i0];
        ((float4*)xs)[i1 + (i1 >> 3)] = ((const float4*)(x + b * DD))[i1];
    }
    // gate: warp w -> expert w; warps 0,1 also experts 4,5
    {
        const float* xr = x + b * DD;
        #pragma unroll
        for (int rep = 0; rep < 2; ++rep) {
            const int e = warp + rep * 4;
            if (rep == 0 || warp < 2) {
                float s0 = 0.f, s1 = 0.f, s2 = 0.f, s3 = 0.f;
                #pragma unroll
                for (int i = 0; i < DD / 128; ++i) {
                    int d = lane + 128 * i;
                    s0 += xr[d]      * gw[(d)      * EE + e];
                    s1 += xr[d + 32] * gw[(d + 32) * EE + e];
                    s2 += xr[d + 64] * gw[(d + 64) * EE + e];
                    s3 += xr[d + 96] * gw[(d + 96) * EE + e];
                }
                float s = (s0 + s1) + (s2 + s3);
                #pragma unroll
                for (int off = 16; off > 0; off >>= 1)
                    s += __shfl_down_sync(0xFFFFFFFFu, s, off);
                if (lane == 0) logit[e] = s + gb[e];
            }
        }
    }
    __syncthreads();

    // ---- top-2 + 2-way softmax (every thread; kept in registers) ----------
    float v[EE];
    #pragma unroll
    for (int e = 0; e < EE; ++e) v[e] = logit[e];
    int i1 = 0; float m1 = v[0];
    #pragma unroll
    for (int e = 1; e < EE; ++e) if (v[e] > m1) { m1 = v[e]; i1 = e; }
    int i2 = -1; float m2 = -INFINITY;
    #pragma unroll
    for (int e = 0; e < EE; ++e) if (e != i1 && v[e] > m2) { m2 = v[e]; i2 = e; }
    const float g1  = 1.0f / (1.0f + __expf(m2 - m1));  // m1 >= m2: stable
    const float gk  = (k == 0) ? g1 : (1.0f - g1);
    const int   e   = (k == 0) ? i1 : i2;
    const int   e0  = i1, e1 = i2;
    const float gk0 = g1, gk1 = 1.0f - g1;

    // Prefetch fc1 bias early (consumed after the reduce; valid for tid<16)
    const float biasv = __ldg(&b1[e * HH + cq * 16 + (tid & 15)]);

    // ---- fc1 (16 cols of quarter cq): dg=tid>>2 (32 d-groups), cg=tid&3 ----
    float4 t;
    {
        const int dg = tid >> 2, cg = tid & 3;
        const float* wbase = w1 + ((size_t)e * DD + dg * 32) * HH + cq * 16 + cg * 4;
        const float* xp = xs + dg * 36;             // padded chunk
        float4 a0 = {0,0,0,0}, a1 = {0,0,0,0}, a2 = {0,0,0,0}, a3 = {0,0,0,0};
        #pragma unroll
        for (int d = 0; d < 32; d += 4) {
            fma4(a0, xp[d + 0], *(const float4*)(wbase + (d + 0) * HH));
            fma4(a1, xp[d + 1], *(const float4*)(wbase + (d + 1) * HH));
            fma4(a2, xp[d + 2], *(const float4*)(wbase + (d + 2) * HH));
            fma4(a3, xp[d + 3], *(const float4*)(wbase + (d + 3) * HH));
        }
        t.x = (a0.x + a1.x) + (a2.x + a3.x);
        t.y = (a0.y + a1.y) + (a2.y + a3.y);
        t.z = (a0.z + a1.z) + (a2.z + a3.z);
        t.w = (a0.w + a1.w) + (a2.w + a3.w);
    }

    // ---- PRE-BARRIER PREFETCH of all phase-2 w2/b2 data into registers -----
    const int g  = tid >> 2;                 // float4 group within O-chunk
    const int s  = tid & 3;                  // k-quarter (16 k each)
    const int obase = oc * 128;              // chunks: 7x128 + 104
    const int ng = (oc < 7) ? 32 : 26;
    const int gg = (g < ng) ? g : (ng - 1);  // clamp for safe loads
    const int o  = obase + gg * 4;

    float4 w2r0[16], w2r1[16];
    const float* p0 = w2 + ((size_t)e0 * HH + s * 16) * OO + o;
    const float* p1 = w2 + ((size_t)e1 * HH + s * 16) * OO + o;
    #pragma unroll
    for (int jj = 0; jj < 16; ++jj) w2r0[jj] = __ldg((const float4*)(p0 + jj * OO));
    #pragma unroll
    for (int jj = 0; jj < 16; ++jj) w2r1[jj] = __ldg((const float4*)(p1 + jj * OO));
    const float4 bb0 = __ldg((const float4*)(b2 + (size_t)e0 * OO + o));
    const float4 bb1 = __ldg((const float4*)(b2 + (size_t)e1 * OO + o));

    // ---- finish fc1: fold 8 d-groups in-warp via shfl, then 4-deep smem ----
    // lane = (dg&7)*4 + cg; fold dg bits (offsets 4,8,16)
    #pragma unroll
    for (int off = 16; off >= 4; off >>= 1) {
        t.x += __shfl_xor_sync(0xFFFFFFFFu, t.x, off);
        t.y += __shfl_xor_sync(0xFFFFFFFFu, t.y, off);
        t.z += __shfl_xor_sync(0xFFFFFFFFu, t.z, off);
        t.w += __shfl_xor_sync(0xFFFFFFFFu, t.w, off);
    }
    if (lane < 4) *(float4*)&part[warp][lane * 4] = t;   // lane = cg
    __syncthreads();

    // ---- broadcast this block's 16 h values into all 8 cluster CTAs' smem --
    if (tid < 16) {
        float sum = biasv + part[0][tid] + part[1][tid] + part[2][tid] + part[3][tid];
        const float hv = gk * fmaxf(sum, 0.0f);
        const unsigned int la = smem_u32(&hs[k * HH + cq * 16 + tid]);
        #pragma unroll
        for (int r = 0; r < CLUSTER; ++r) dsmem_store(la, r, hv);
    }

    // ---- CLUSTER BARRIER: h now complete in every CTA's local smem ---------
    asm volatile("barrier.cluster.arrive.aligned;" ::: "memory");
    asm volatile("barrier.cluster.wait.aligned;"   ::: "memory");

    // ---- PHASE 2: h from LOCAL smem, w2/b2 from registers ------------------
    float4 acc = {0, 0, 0, 0};
    {
        const float4* h0p = (const float4*)(hs + s * 16);
        const float4* h1p = (const float4*)(hs + HH + s * 16);
        #pragma unroll
        for (int q = 0; q < 4; ++q) {
            float4 hq = h0p[q];
            fma4(acc, hq.x, w2r0[q * 4 + 0]);
            fma4(acc, hq.y, w2r0[q * 4 + 1]);
            fma4(acc, hq.z, w2r0[q * 4 + 2]);
            fma4(acc, hq.w, w2r0[q * 4 + 3]);
        }
        #pragma unroll
        for (int q = 0; q < 4; ++q) {
            float4 hq = h1p[q];
            fma4(acc, hq.x, w2r1[q * 4 + 0]);
            fma4(acc, hq.y, w2r1[q * 4 + 1]);
            fma4(acc, hq.z, w2r1[q * 4 + 2]);
            fma4(acc, hq.w, w2r1[q * 4 + 3]);
        }
    }

    // reduce across the 4 k-quarters (lanes 4g+s share a warp)
    #pragma unroll
    for (int off = 1; off <= 2; off <<= 1) {
        acc.x += __shfl_xor_sync(0xFFFFFFFFu, acc.x, off);
        acc.y += __shfl_xor_sync(0xFFFFFFFFu, acc.y, off);
        acc.z += __shfl_xor_sync(0xFFFFFFFFu, acc.z, off);
        acc.w += __shfl_xor_sync(0xFFFFFFFFu, acc.w, off);
    }

    if (g < ng && s == 0) {
        float4 r;
        r.x = acc.x + gk0 * bb0.x + gk1 * bb1.x;
        r.y = acc.y + gk0 * bb0.y + gk1 * bb1.y;
        r.z = acc.z + gk0 * bb0.z + gk1 * bb1.z;
        r.w = acc.w + gk0 * bb0.w + gk1 * bb1.w;
        *(float4*)(out + b * OO + o) = r;
    }
}

// Inputs: x, gate_w, gate_b, w1, b1, w2, b2. Output: f32 [32,1000]
extern "C" void kernel_launch(void* const* d_in, const int* in_sizes, int n_in,
                              void* d_out, int out_size) {
    const float* x  = (const float*)d_in[0];
    const float* gw = (const float*)d_in[1];
    const float* gb = (const float*)d_in[2];
    const float* w1 = (const float*)d_in[3];
    const float* b1 = (const float*)d_in[4];
    const float* w2 = (const float*)d_in[5];
    const float* b2 = (const float*)d_in[6];
    float* out = (float*)d_out;

    moe_fused<<<NBLK, NTHR>>>(x, gw, gb, w1, b1, w2, b2, out);
}

// round 15
// speedup vs baseline: 1.0743x; 1.0743x over previous
#include <cuda_runtime.h>
#include <cstdint>
#include <math.h>

#define BB 32
#define DD 1024
#define HH 64
#define OO 1000
#define EE 6
#define NBLK 128
#define NTHR 256
#define CLUSTER 4

__device__ __forceinline__ void fma4(float4& acc, float v, const float4& w) {
    acc.x += v * w.x; acc.y += v * w.y; acc.z += v * w.z; acc.w += v * w.w;
}

__device__ __forceinline__ unsigned int smem_u32(const void* p) {
    unsigned int a;
    asm("{ .reg .u64 t; cvta.to.shared.u64 t, %1; cvt.u32.u64 %0, t; }"
        : "=r"(a) : "l"(p));
    return a;
}

// Store one float into the same smem offset of cluster CTA `rank`.
__device__ __forceinline__ void dsmem_store(unsigned int local_addr, int rank, float v) {
    unsigned int rem;
    asm volatile("mapa.shared::cluster.u32 %0, %1, %2;"
                 : "=r"(rem) : "r"(local_addr), "r"(rank));
    asm volatile("st.shared::cluster.f32 [%0], %1;"
                 :: "r"(rem), "f"(v) : "memory");
}

__global__ void __launch_bounds__(NTHR) __cluster_dims__(CLUSTER, 1, 1)
moe_fused(const float* __restrict__ x,
          const float* __restrict__ gw,
          const float* __restrict__ gb,
          const float* __restrict__ w1,
          const float* __restrict__ b1,
          const float* __restrict__ w2,
          const float* __restrict__ b2,
          float* __restrict__ out) {
    const int bid = blockIdx.x;
    const int tid = threadIdx.x;
    const int warp = tid >> 5, lane = tid & 31;

    __shared__ __align__(16) float part[8][32];     // fc1 cross-warp partials
    __shared__ __align__(16) float hs[2 * HH];      // row b's full h (both slots)
    __shared__ float logit[EE];

    // Cluster = the 4 blocks of row b. Phase-1 role (k, ch), phase-2 role oc.
    const int b = bid >> 2, k = (bid >> 1) & 1, ch = bid & 1;
    const int oc = bid & 3;

    // ---- x chunk STRAIGHT TO REGISTERS at cycle 0 (no smem stage, no sync) -
    const int dg = tid >> 3, cg = tid & 7;          // 32 d-groups x 8 col-groups
    float4 xr4[8];
    {
        const float4* xcp = (const float4*)(x + b * DD + dg * 32);
        #pragma unroll
        for (int i = 0; i < 8; ++i) xr4[i] = __ldg(xcp + i);
    }

    // ---- gate logits from global x (L1-shared with the chunk loads) --------
    if (warp < EE) {
        const float* xr = x + b * DD;
        float s0 = 0.f, s1 = 0.f, s2 = 0.f, s3 = 0.f;
        #pragma unroll
        for (int i = 0; i < DD / 128; ++i) {        // 4-way chain split
            int d = lane + 128 * i;
            s0 += xr[d]      * gw[(d)      * EE + warp];
            s1 += xr[d + 32] * gw[(d + 32) * EE + warp];
            s2 += xr[d + 64] * gw[(d + 64) * EE + warp];
            s3 += xr[d + 96] * gw[(d + 96) * EE + warp];
        }
        float s = (s0 + s1) + (s2 + s3);
        #pragma unroll
        for (int off = 16; off > 0; off >>= 1)
            s += __shfl_down_sync(0xFFFFFFFFu, s, off);
        if (lane == 0) logit[warp] = s + gb[warp];
    }
    __syncthreads();                                // publishes ONLY the logits

    // ---- top-2 + 2-way softmax (every thread; kept in registers) ----------
    float v[EE];
    #pragma unroll
    for (int e = 0; e < EE; ++e) v[e] = logit[e];
    int i1 = 0; float m1 = v[0];
    #pragma unroll
    for (int e = 1; e < EE; ++e) if (v[e] > m1) { m1 = v[e]; i1 = e; }
    int i2 = -1; float m2 = -INFINITY;
    #pragma unroll
    for (int e = 0; e < EE; ++e) if (e != i1 && v[e] > m2) { m2 = v[e]; i2 = e; }
    const float g1  = 1.0f / (1.0f + __expf(m2 - m1));  // m1 >= m2: stable
    const float gk  = (k == 0) ? g1 : (1.0f - g1);
    const int   e   = (k == 0) ? i1 : i2;
    const int   e0  = i1, e1 = i2;
    const float gk0 = g1, gk1 = 1.0f - g1;

    // Prefetch fc1 bias early (consumed after the reduce)
    const float biasv = __ldg(&b1[e * HH + ch * 32 + (tid & 31)]);

    // ---- fc1 (32 cols of half ch): x from registers, w1 from global --------
    float4 t;
    {
        const float* wbase = w1 + ((size_t)e * DD + dg * 32) * HH + ch * 32 + cg * 4;
        float4 a0 = {0,0,0,0}, a1 = {0,0,0,0}, a2 = {0,0,0,0}, a3 = {0,0,0,0};
        #pragma unroll
        for (int d4 = 0; d4 < 8; ++d4) {
            const float4 xv = xr4[d4];
            fma4(a0, xv.x, *(const float4*)(wbase + (d4 * 4 + 0) * HH));
            fma4(a1, xv.y, *(const float4*)(wbase + (d4 * 4 + 1) * HH));
            fma4(a2, xv.z, *(const float4*)(wbase + (d4 * 4 + 2) * HH));
            fma4(a3, xv.w, *(const float4*)(wbase + (d4 * 4 + 3) * HH));
        }
        t.x = (a0.x + a1.x) + (a2.x + a3.x);
        t.y = (a0.y + a1.y) + (a2.y + a3.y);
        t.z = (a0.z + a1.z) + (a2.z + a3.z);
        t.w = (a0.w + a1.w) + (a2.w + a3.w);
    }

    // ---- PRE-BARRIER PREFETCH of all phase-2 w2/b2 data into registers -----
    const int g  = tid >> 2;                 // float4 group within O-chunk
    const int s  = tid & 3;                  // k-quarter (16 k each)
    const int olen = (oc < 3) ? 256 : 232;
    const int ng = olen >> 2;
    const int gg = (g < ng) ? g : (ng - 1);  // clamp for safe loads
    const int o  = oc * 256 + gg * 4;

    float4 w2r0[16], w2r1[16];
    const float* p0 = w2 + ((size_t)e0 * HH + s * 16) * OO + o;
    const float* p1 = w2 + ((size_t)e1 * HH + s * 16) * OO + o;
    #pragma unroll
    for (int j = 0; j < 16; ++j) w2r0[j] = __ldg((const float4*)(p0 + j * OO));
    #pragma unroll
    for (int j = 0; j < 16; ++j) w2r1[j] = __ldg((const float4*)(p1 + j * OO));
    const float4 bb0 = __ldg((const float4*)(b2 + (size_t)e0 * OO + o));
    const float4 bb1 = __ldg((const float4*)(b2 + (size_t)e1 * OO + o));

    // ---- finish fc1: fold 4 d-groups in-warp via shfl, then 8-deep smem ----
    #pragma unroll
    for (int off = 16; off >= 8; off >>= 1) {
        t.x += __shfl_xor_sync(0xFFFFFFFFu, t.x, off);
        t.y += __shfl_xor_sync(0xFFFFFFFFu, t.y, off);
        t.z += __shfl_xor_sync(0xFFFFFFFFu, t.z, off);
        t.w += __shfl_xor_sync(0xFFFFFFFFu, t.w, off);
    }
    if (lane < 8) *(float4*)&part[warp][lane * 4] = t;
    __syncthreads();

    // ---- broadcast this block's 32 h values into all 4 cluster CTAs' smem --
    if (tid < 32) {
        float sum = biasv;
        #pragma unroll
        for (int w = 0; w < 8; ++w) sum += part[w][tid];
        const float hv = gk * fmaxf(sum, 0.0f);
        const unsigned int la = smem_u32(&hs[k * HH + ch * 32 + tid]);
        #pragma unroll
        for (int r = 0; r < CLUSTER; ++r) dsmem_store(la, r, hv);
    }

    // ---- CLUSTER BARRIER: h now complete in every CTA's local smem ---------
    asm volatile("barrier.cluster.arrive.aligned;" ::: "memory");
    asm volatile("barrier.cluster.wait.aligned;"   ::: "memory");

    // ---- PHASE 2: h from LOCAL smem, w2/b2 from registers (2 acc chains) ---
    float4 acc0 = {0, 0, 0, 0}, acc1 = {0, 0, 0, 0};
    {
        const float4* h0p = (const float4*)(hs + s * 16);
        const float4* h1p = (const float4*)(hs + HH + s * 16);
        #pragma unroll
        for (int q = 0; q < 4; ++q) {
            float4 hq = h0p[q];
            fma4(acc0, hq.x, w2r0[q * 4 + 0]);
            fma4(acc0, hq.y, w2r0[q * 4 + 1]);
            fma4(acc0, hq.z, w2r0[q * 4 + 2]);
            fma4(acc0, hq.w, w2r0[q * 4 + 3]);
        }
        #pragma unroll
        for (int q = 0; q < 4; ++q) {
            float4 hq = h1p[q];
            fma4(acc1, hq.x, w2r1[q * 4 + 0]);
            fma4(acc1, hq.y, w2r1[q * 4 + 1]);
            fma4(acc1, hq.z, w2r1[q * 4 + 2]);
            fma4(acc1, hq.w, w2r1[q * 4 + 3]);
        }
    }
    float4 acc;
    acc.x = acc0.x + acc1.x;
    acc.y = acc0.y + acc1.y;
    acc.z = acc0.z + acc1.z;
    acc.w = acc0.w + acc1.w;

    // reduce across the 4 k-quarters (lanes 4g+s share a warp)
    #pragma unroll
    for (int off = 1; off <= 2; off <<= 1) {
        acc.x += __shfl_xor_sync(0xFFFFFFFFu, acc.x, off);
        acc.y += __shfl_xor_sync(0xFFFFFFFFu, acc.y, off);
        acc.z += __shfl_xor_sync(0xFFFFFFFFu, acc.z, off);
        acc.w += __shfl_xor_sync(0xFFFFFFFFu, acc.w, off);
    }

    if (g < ng && s == 0) {
        float4 r;
        r.x = acc.x + gk0 * bb0.x + gk1 * bb1.x;
        r.y = acc.y + gk0 * bb0.y + gk1 * bb1.y;
        r.z = acc.z + gk0 * bb0.z + gk1 * bb1.z;
        r.w = acc.w + gk0 * bb0.w + gk1 * bb1.w;
        *(float4*)(out + b * OO + o) = r;
    }
}

// Inputs: x, gate_w, gate_b, w1, b1, w2, b2. Output: f32 [32,1000]
extern "C" void kernel_launch(void* const* d_in, const int* in_sizes, int n_in,
                              void* d_out, int out_size) {
    const float* x  = (const float*)d_in[0];
    const float* gw = (const float*)d_in[1];
    const float* gb = (const float*)d_in[2];
    const float* w1 = (const float*)d_in[3];
    const float* b1 = (const float*)d_in[4];
    const float* w2 = (const float*)d_in[5];
    const float* b2 = (const float*)d_in[6];
    float* out = (float*)d_out;

    moe_fused<<<NBLK, NTHR>>>(x, gw, gb, w1, b1, w2, b2, out);
}

// round 16
// speedup vs baseline: 1.1051x; 1.0287x over previous
#include <cuda_runtime.h>
#include <cstdint>
#include <math.h>

#define BB 32
#define DD 1024
#define HH 64
#define OO 1000
#define EE 6
#define NBLK 128
#define NTHR 256
#define CLUSTER 4

__device__ __forceinline__ void fma4(float4& acc, float v, const float4& w) {
    acc.x += v * w.x; acc.y += v * w.y; acc.z += v * w.z; acc.w += v * w.w;
}

__global__ void __launch_bounds__(NTHR, 1) __cluster_dims__(CLUSTER, 1, 1)
moe_fused(const float* __restrict__ x,
          const float* __restrict__ gw,
          const float* __restrict__ gb,
          const float* __restrict__ w1,
          const float* __restrict__ b1,
          const float* __restrict__ w2,
          const float* __restrict__ b2,
          float* __restrict__ out) {
    const int bid = blockIdx.x;
    const int tid = threadIdx.x;
    const int warp = tid >> 5, lane = tid & 31;

    __shared__ __align__(16) float part[8][32];     // fc1 cross-warp partials
    __shared__ __align__(16) float hs[32];          // this block's h cols (gate-scaled)
    __shared__ float logit[EE];

    // Cluster = the 4 blocks of row b; roles: expert slot k, col-half ch.
    const int b = bid >> 2, j = bid & 3;
    const int k = j >> 1, ch = j & 1;

    // ---- zero my quarter of out[b,:], then non-blocking cluster arrive -----
    if (tid < 250) out[b * OO + j * 250 + tid] = 0.0f;
    asm volatile("barrier.cluster.arrive.aligned;" ::: "memory");

    // ---- x chunk straight to registers (no smem stage) ---------------------
    const int dg = tid >> 3, cg = tid & 7;          // 32 d-groups x 8 col-groups
    float4 xr4[8];
    {
        const float4* xcp = (const float4*)(x + b * DD + dg * 32);
        #pragma unroll
        for (int i = 0; i < 8; ++i) xr4[i] = __ldg(xcp + i);
    }

    // ---- gate logits from global x -----------------------------------------
    if (warp < EE) {
        const float* xr = x + b * DD;
        float s0 = 0.f, s1 = 0.f, s2 = 0.f, s3 = 0.f;
        #pragma unroll
        for (int i = 0; i < DD / 128; ++i) {        // 4-way chain split
            int d = lane + 128 * i;
            s0 += xr[d]      * gw[(d)      * EE + warp];
            s1 += xr[d + 32] * gw[(d + 32) * EE + warp];
            s2 += xr[d + 64] * gw[(d + 64) * EE + warp];
            s3 += xr[d + 96] * gw[(d + 96) * EE + warp];
        }
        float s = (s0 + s1) + (s2 + s3);
        #pragma unroll
        for (int off = 16; off > 0; off >>= 1)
            s += __shfl_down_sync(0xFFFFFFFFu, s, off);
        if (lane == 0) logit[warp] = s + gb[warp];
    }
    __syncthreads();                                // publishes the 6 logits

    // ---- top-2 + 2-way softmax (every thread; registers only) -------------
    float v[EE];
    #pragma unroll
    for (int e = 0; e < EE; ++e) v[e] = logit[e];
    int i1 = 0; float m1 = v[0];
    #pragma unroll
    for (int e = 1; e < EE; ++e) if (v[e] > m1) { m1 = v[e]; i1 = e; }
    int i2 = -1; float m2 = -INFINITY;
    #pragma unroll
    for (int e = 0; e < EE; ++e) if (e != i1 && v[e] > m2) { m2 = v[e]; i2 = e; }
    const float g1 = 1.0f / (1.0f + __expf(m2 - m1));   // m1 >= m2: stable
    const float gk = (k == 0) ? g1 : (1.0f - g1);
    const int   e  = (k == 0) ? i1 : i2;

    // Prefetch fc1 bias early (consumed after the reduce)
    const float biasv = __ldg(&b1[e * HH + ch * 32 + (tid & 31)]);

    // ---- fc1 (32 cols of half ch): x from registers, w1 from global --------
    float4 t;
    {
        const float* wbase = w1 + ((size_t)e * DD + dg * 32) * HH + ch * 32 + cg * 4;
        float4 a0 = {0,0,0,0}, a1 = {0,0,0,0}, a2 = {0,0,0,0}, a3 = {0,0,0,0};
        #pragma unroll
        for (int d4 = 0; d4 < 8; ++d4) {
            const float4 xv = xr4[d4];
            fma4(a0, xv.x, *(const float4*)(wbase + (d4 * 4 + 0) * HH));
            fma4(a1, xv.y, *(const float4*)(wbase + (d4 * 4 + 1) * HH));
            fma4(a2, xv.z, *(const float4*)(wbase + (d4 * 4 + 2) * HH));
            fma4(a3, xv.w, *(const float4*)(wbase + (d4 * 4 + 3) * HH));
        }
        t.x = (a0.x + a1.x) + (a2.x + a3.x);
        t.y = (a0.y + a1.y) + (a2.y + a3.y);
        t.z = (a0.z + a1.z) + (a2.z + a3.z);
        t.w = (a0.w + a1.w) + (a2.w + a3.w);
    }

    // ---- prefetch w2 rows (MY expert, MY 32 k-cols) for outputs 4g..4g+3 ---
    const int g = (tid < 250) ? tid : 249;          // clamp for safe loads
    float4 w2r[32];
    {
        const float* wp = w2 + ((size_t)e * HH + ch * 32) * OO + g * 4;
        #pragma unroll
        for (int c = 0; c < 32; ++c)
            w2r[c] = __ldg((const float4*)(wp + c * OO));
    }
    float4 bb = {0, 0, 0, 0};
    if (ch == 0) bb = __ldg((const float4*)(b2 + (size_t)e * OO + g * 4));

    // ---- finish fc1: fold 4 d-groups in-warp via shfl, then 8-deep smem ----
    #pragma unroll
    for (int off = 16; off >= 8; off >>= 1) {
        t.x += __shfl_xor_sync(0xFFFFFFFFu, t.x, off);
        t.y += __shfl_xor_sync(0xFFFFFFFFu, t.y, off);
        t.z += __shfl_xor_sync(0xFFFFFFFFu, t.z, off);
        t.w += __shfl_xor_sync(0xFFFFFFFFu, t.w, off);
    }
    if (lane < 8) *(float4*)&part[warp][lane * 4] = t;
    __syncthreads();
    if (tid < 32) {
        float sum = biasv;
        #pragma unroll
        for (int w = 0; w < 8; ++w) sum += part[w][tid];
        hs[tid] = gk * fmaxf(sum, 0.0f);            // gate pre-applied, LOCAL only
    }
    __syncthreads();

    // ---- fc2 partial: my 32 k-cols x my 4 outputs (h broadcast from smem) --
    float4 a0 = {0,0,0,0}, a1 = {0,0,0,0}, a2 = {0,0,0,0}, a3 = {0,0,0,0};
    #pragma unroll
    for (int c = 0; c < 32; c += 4) {
        fma4(a0, hs[c + 0], w2r[c + 0]);
        fma4(a1, hs[c + 1], w2r[c + 1]);
        fma4(a2, hs[c + 2], w2r[c + 2]);
        fma4(a3, hs[c + 3], w2r[c + 3]);
    }
    float4 acc;
    acc.x = (a0.x + a1.x) + (a2.x + a3.x);
    acc.y = (a0.y + a1.y) + (a2.y + a3.y);
    acc.z = (a0.z + a1.z) + (a2.z + a3.z);
    acc.w = (a0.w + a1.w) + (a2.w + a3.w);
    if (ch == 0) {                                  // gate-weighted bias once per slot
        acc.x += gk * bb.x; acc.y += gk * bb.y;
        acc.z += gk * bb.z; acc.w += gk * bb.w;
    }

    // ---- wait for cluster-mates' zeroing (arrived ages ago: fast-path) -----
    asm volatile("barrier.cluster.wait.aligned;" ::: "memory");

    // ---- accumulate into out: 4 commutative adds per element ---------------
    if (tid < 250) {
        float* op = out + b * OO + g * 4;
        atomicAdd(op + 0, acc.x);
        atomicAdd(op + 1, acc.y);
        atomicAdd(op + 2, acc.z);
        atomicAdd(op + 3, acc.w);
    }
}

// Inputs: x, gate_w, gate_b, w1, b1, w2, b2. Output: f32 [32,1000]
extern "C" void kernel_launch(void* const* d_in, const int* in_sizes, int n_in,
                              void* d_out, int out_size) {
    const float* x  = (const float*)d_in[0];
    const float* gw = (const float*)d_in[1];
    const float* gb = (const float*)d_in[2];
    const float* w1 = (const float*)d_in[3];
    const float* b1 = (const float*)d_in[4];
    const float* w2 = (const float*)d_in[5];
    const float* b2 = (const float*)d_in[6];
    float* out = (float*)d_out;

    moe_fused<<<NBLK, NTHR>>>(x, gw, gb, w1, b1, w2, b2, out);
}